// round 15
// baseline (speedup 1.0000x reference)
#include <cuda_runtime.h>
#include <cuda_bf16.h>
#include <cuda_fp16.h>
#include <mma.h>
#include <math.h>
#include <stdint.h>

using namespace nvcuda;

#define HDIM 128
#define MAXN 100000
#define MAXE 1600000
#define NUM_GRAPHS 100
#define SCAN_BLK 256
#define MAX_BLKS 512

// smem layout (bytes). ldm = 136 bf16 (272B rows)
#define LDA 136
#define SA_HI 0
#define SA_LO (128 * LDA * 2)
#define SB_HI (2 * 128 * LDA * 2)
#define SB_LO (3 * 128 * LDA * 2)
#define SMEM_MMA (4 * 128 * LDA * 2)   // 139264 bytes

// ---------------- scratch (no allocation allowed) ----------------
__device__ __half g_Ya[MAXN * HDIM];               // Y ping (GEMM1/3 out)
__device__ __half g_Yb[MAXN * HDIM];               // Y pong (GEMM2 out)
__device__ __half g_u[MAXN * HDIM];                // u = ns*h / final h (fp16)
__device__ __nv_bfloat16 g_Whi[3 * HDIM * HDIM];   // W hi  [k][n]
__device__ __nv_bfloat16 g_Wlo[3 * HDIM * HDIM];   // W lo  [k][n]
__device__ float g_ns[MAXN];
__device__ float g_nd[MAXN];
__device__ int   g_odeg[MAXN];
__device__ int   g_ideg[MAXN];
__device__ int   g_off[MAXN];
__device__ int   g_cursor[MAXN];
__device__ int   g_csr_src[MAXE];
__device__ int   g_bsums[MAX_BLKS];

// ---------------- degree counting ----------------
__global__ void zero_deg_kernel(int* odeg, int* ideg, int N) {
    int i = blockIdx.x * blockDim.x + threadIdx.x;
    if (i < N) { odeg[i] = 0; ideg[i] = 0; }
}

__global__ void count_deg_kernel(const int* __restrict__ src,
                                 const int* __restrict__ dst,
                                 int* odeg, int* ideg, int E) {
    int i = blockIdx.x * blockDim.x + threadIdx.x;
    if (i < E) {
        atomicAdd(&odeg[src[i]], 1);
        atomicAdd(&ideg[dst[i]], 1);
    }
}

__global__ void norms_kernel(const int* __restrict__ odeg,
                             const int* __restrict__ ideg,
                             float* ns, float* nd, int N) {
    int i = blockIdx.x * blockDim.x + threadIdx.x;
    if (i < N) {
        ns[i] = rsqrtf((float)(odeg[i] + 1));
        nd[i] = rsqrtf((float)(ideg[i] + 1));
    }
}

// ---------------- prefix sum ----------------
__global__ void blocksum_kernel(const int* __restrict__ deg, int* bsums, int N) {
    __shared__ int s[SCAN_BLK];
    int i = blockIdx.x * SCAN_BLK + threadIdx.x;
    s[threadIdx.x] = (i < N) ? deg[i] : 0;
    __syncthreads();
    for (int o = SCAN_BLK / 2; o > 0; o >>= 1) {
        if (threadIdx.x < o) s[threadIdx.x] += s[threadIdx.x + o];
        __syncthreads();
    }
    if (threadIdx.x == 0) bsums[blockIdx.x] = s[0];
}

__global__ void scan_bsums_kernel(int* bsums, int nblk) {
    __shared__ int s[MAX_BLKS];
    int t = threadIdx.x;
    int v = (t < nblk) ? bsums[t] : 0;
    s[t] = v;
    __syncthreads();
    for (int o = 1; o < MAX_BLKS; o <<= 1) {
        int add = (t >= o) ? s[t - o] : 0;
        __syncthreads();
        s[t] += add;
        __syncthreads();
    }
    if (t < nblk) bsums[t] = s[t] - v;
}

__global__ void write_offsets_kernel(const int* __restrict__ deg,
                                     const int* __restrict__ bsums,
                                     int* off, int* cursor, int N) {
    __shared__ int s[SCAN_BLK];
    int i = blockIdx.x * SCAN_BLK + threadIdx.x;
    int t = threadIdx.x;
    int v = (i < N) ? deg[i] : 0;
    s[t] = v;
    __syncthreads();
    for (int o = 1; o < SCAN_BLK; o <<= 1) {
        int add = (t >= o) ? s[t - o] : 0;
        __syncthreads();
        s[t] += add;
        __syncthreads();
    }
    if (i < N) {
        int ofs = bsums[blockIdx.x] + s[t] - v;
        off[i] = ofs;
        cursor[i] = ofs;
    }
}

__global__ void fill_csr_kernel(const int* __restrict__ src,
                                const int* __restrict__ dst,
                                int* cursor, int* csr_src, int E) {
    int i = blockIdx.x * blockDim.x + threadIdx.x;
    if (i < E) {
        int slot = atomicAdd(&cursor[dst[i]], 1);
        csr_src[slot] = src[i];
    }
}

// ---------------- convert W: hi/lo split ----------------
__global__ void convertW_kernel(const float* __restrict__ W1,
                                const float* __restrict__ W2,
                                const float* __restrict__ W3,
                                __nv_bfloat16* __restrict__ Whi,
                                __nv_bfloat16* __restrict__ Wlo) {
    int i = blockIdx.x * blockDim.x + threadIdx.x;
    if (i >= 3 * HDIM * HDIM) return;
    int w = i / (HDIM * HDIM);
    int r = i % (HDIM * HDIM);
    const float* W = (w == 0) ? W1 : ((w == 1) ? W2 : W3);
    float v = W[r];
    __nv_bfloat16 hi = __float2bfloat16(v);
    Whi[i] = hi;
    Wlo[i] = __float2bfloat16(v - __bfloat162float(hi));
}

// ---------------- convert X (fp32 -> fp16) ----------------
__global__ void convertX_kernel(const float* __restrict__ X,
                                __half* __restrict__ Xh, int n4) {
    int i = blockIdx.x * blockDim.x + threadIdx.x;
    if (i >= n4) return;
    float4 v = ((const float4*)X)[i];
    __half2 p0 = __floats2half2_rn(v.x, v.y);
    __half2 p1 = __floats2half2_rn(v.z, v.w);
    uint2 u;
    u.x = *(uint32_t*)&p0;
    u.y = *(uint32_t*)&p1;
    ((uint2*)Xh)[i] = u;
}

// ---------------- wmma split-bf16 GEMM: fp16 in, fp16 out ----------------
// rows [rowbase + bid*128, ...)
__global__ void __launch_bounds__(512)
mma_gemm_kernel(const __half* __restrict__ A,
                const __nv_bfloat16* __restrict__ Whi,
                const __nv_bfloat16* __restrict__ Wlo,
                __half* __restrict__ Y, int rowbase, int N) {
    extern __shared__ char smem[];
    __nv_bfloat16* sAhi = (__nv_bfloat16*)(smem + SA_HI);
    __nv_bfloat16* sAlo = (__nv_bfloat16*)(smem + SA_LO);
    __nv_bfloat16* sBhi = (__nv_bfloat16*)(smem + SB_HI);
    __nv_bfloat16* sBlo = (__nv_bfloat16*)(smem + SB_LO);

    const int tid = threadIdx.x;
    const int base = rowbase + blockIdx.x * 128;

    const uint4* WH4 = (const uint4*)Whi;
    const uint4* WL4 = (const uint4*)Wlo;
    const uint4* A4 = (const uint4*)A;
    const uint4 z4 = make_uint4(0, 0, 0, 0);
    #pragma unroll
    for (int i = tid; i < 128 * 16; i += 512) {
        int row = i >> 4, c8 = i & 15;
        int gr = base + row;
        uint4 a = (gr < N) ? A4[(size_t)gr * 16 + c8] : z4;
        const __half2* hp = (const __half2*)&a;
        uint32_t hiw[4], low[4];
        #pragma unroll
        for (int j = 0; j < 4; j++) {
            float2 f = __half22float2(hp[j]);
            __nv_bfloat16 b0 = __float2bfloat16(f.x);
            __nv_bfloat16 b1 = __float2bfloat16(f.y);
            __nv_bfloat162 bh = __halves2bfloat162(b0, b1);
            __nv_bfloat162 bl = __halves2bfloat162(
                __float2bfloat16(f.x - __bfloat162float(b0)),
                __float2bfloat16(f.y - __bfloat162float(b1)));
            hiw[j] = *(uint32_t*)&bh;
            low[j] = *(uint32_t*)&bl;
        }
        *(uint4*)&sAhi[row * LDA + c8 * 8] = make_uint4(hiw[0], hiw[1], hiw[2], hiw[3]);
        *(uint4*)&sAlo[row * LDA + c8 * 8] = make_uint4(low[0], low[1], low[2], low[3]);
        *(uint4*)&sBhi[row * LDA + c8 * 8] = WH4[i];
        *(uint4*)&sBlo[row * LDA + c8 * 8] = WL4[i];
    }
    __syncthreads();

    const int wid = tid >> 5;
    const int wm = wid & 3;
    const int wn = wid >> 2;

    wmma::fragment<wmma::accumulator, 16, 16, 16, float> acc[2][2];
    #pragma unroll
    for (int i = 0; i < 2; i++)
        #pragma unroll
        for (int j = 0; j < 2; j++)
            wmma::fill_fragment(acc[i][j], 0.0f);

    #pragma unroll
    for (int ks = 0; ks < 8; ks++) {
        wmma::fragment<wmma::matrix_a, 16, 16, 16, __nv_bfloat16, wmma::row_major> ahi[2], alo[2];
        wmma::fragment<wmma::matrix_b, 16, 16, 16, __nv_bfloat16, wmma::row_major> bhi[2], blo[2];
        #pragma unroll
        for (int i = 0; i < 2; i++) {
            wmma::load_matrix_sync(ahi[i], &sAhi[(wm * 32 + i * 16) * LDA + ks * 16], LDA);
            wmma::load_matrix_sync(alo[i], &sAlo[(wm * 32 + i * 16) * LDA + ks * 16], LDA);
        }
        #pragma unroll
        for (int j = 0; j < 2; j++) {
            wmma::load_matrix_sync(bhi[j], &sBhi[(ks * 16) * LDA + wn * 32 + j * 16], LDA);
            wmma::load_matrix_sync(blo[j], &sBlo[(ks * 16) * LDA + wn * 32 + j * 16], LDA);
        }
        #pragma unroll
        for (int i = 0; i < 2; i++)
            #pragma unroll
            for (int j = 0; j < 2; j++) {
                wmma::mma_sync(acc[i][j], ahi[i], bhi[j], acc[i][j]);
                wmma::mma_sync(acc[i][j], ahi[i], blo[j], acc[i][j]);
                wmma::mma_sync(acc[i][j], alo[i], bhi[j], acc[i][j]);
            }
    }

    __syncthreads();
    float* fs = (float*)smem;   // 64 KB staging
    #pragma unroll
    for (int i = 0; i < 2; i++)
        #pragma unroll
        for (int j = 0; j < 2; j++)
            wmma::store_matrix_sync(
                fs + (wm * 32 + i * 16) * HDIM + wn * 32 + j * 16,
                acc[i][j], HDIM, wmma::mem_row_major);
    __syncthreads();
    uint2* Y2 = (uint2*)Y;
    const float4* fs4 = (const float4*)fs;
    #pragma unroll
    for (int i = tid; i < 128 * 32; i += 512) {
        int row = i >> 5;
        int gr = base + row;
        if (gr < N) {
            float4 v = fs4[i];
            __half2 p0 = __floats2half2_rn(v.x, v.y);
            __half2 p1 = __floats2half2_rn(v.z, v.w);
            uint2 u;
            u.x = *(uint32_t*)&p0;
            u.y = *(uint32_t*)&p1;
            Y2[(size_t)gr * 32 + (i & 31)] = u;
        }
    }
}

// ---------------- fp16 row-chunk load: 4 dims per lane ----------------
__device__ __forceinline__ float4 ldY4(const uint2* __restrict__ Y2,
                                       int n, int lane) {
    uint2 u = __ldg(&Y2[(size_t)n * 32 + lane]);
    __half2 a = *(__half2*)&u.x;
    __half2 b = *(__half2*)&u.y;
    float2 fa = __half22float2(a);
    float2 fb = __half22float2(b);
    return make_float4(fa.x, fa.y, fb.x, fb.y);
}

// ---------------- fused gather + epilogue + next-layer input prep ----------
// mode 0: per-edge ns (layer 1), out u = ns*h fp16
// mode 1: pre-scaled input, out u = ns*h fp16
// mode 2: pre-scaled input, out h fp16 (final, for pool)
// processes nodes [nbase, nend)
__global__ void gather_kernel(const __half* __restrict__ Z,
                              const int* __restrict__ off,
                              const int* __restrict__ ideg,
                              const int* __restrict__ csr_src,
                              const float* __restrict__ ns,
                              const float* __restrict__ nd,
                              const float* __restrict__ b,
                              __half* __restrict__ u,
                              int mode, int nbase, int nend) {
    int gt = blockIdx.x * blockDim.x + threadIdx.x;
    int n = nbase + (gt >> 5);
    int lane = threadIdx.x & 31;
    if (n >= nend) return;

    const uint2* Z2 = (const uint2*)Z;
    float4 acc = ldY4(Z2, n, lane);
    if (mode == 0) {
        float sn = ns[n];
        acc.x *= sn; acc.y *= sn; acc.z *= sn; acc.w *= sn;
    }
    int o = off[n];
    int d = ideg[n];

    int e = 0;
    if (mode == 0) {
        for (; e + 8 <= d; e += 8) {
            int s[8]; float nn[8]; float4 v[8];
            #pragma unroll
            for (int k = 0; k < 8; k++) s[k] = csr_src[o + e + k];
            #pragma unroll
            for (int k = 0; k < 8; k++) nn[k] = __ldg(&ns[s[k]]);
            #pragma unroll
            for (int k = 0; k < 8; k++) v[k] = ldY4(Z2, s[k], lane);
            #pragma unroll
            for (int k = 0; k < 8; k++) {
                acc.x += v[k].x * nn[k]; acc.y += v[k].y * nn[k];
                acc.z += v[k].z * nn[k]; acc.w += v[k].w * nn[k];
            }
        }
        for (; e < d; e++) {
            int s = csr_src[o + e];
            float nn = __ldg(&ns[s]);
            float4 v = ldY4(Z2, s, lane);
            acc.x += v.x * nn; acc.y += v.y * nn;
            acc.z += v.z * nn; acc.w += v.w * nn;
        }
    } else {
        for (; e + 8 <= d; e += 8) {
            int s[8]; float4 v[8];
            #pragma unroll
            for (int k = 0; k < 8; k++) s[k] = csr_src[o + e + k];
            #pragma unroll
            for (int k = 0; k < 8; k++) v[k] = ldY4(Z2, s[k], lane);
            #pragma unroll
            for (int k = 0; k < 8; k++) {
                acc.x += v[k].x; acc.y += v[k].y;
                acc.z += v[k].z; acc.w += v[k].w;
            }
        }
        for (; e < d; e++) {
            int s = csr_src[o + e];
            float4 v = ldY4(Z2, s, lane);
            acc.x += v.x; acc.y += v.y; acc.z += v.z; acc.w += v.w;
        }
    }

    float sc = nd[n];
    float4 bb = ((const float4*)b)[lane];
    float hx = fmaxf(acc.x * sc + bb.x, 0.f);
    float hy = fmaxf(acc.y * sc + bb.y, 0.f);
    float hz = fmaxf(acc.z * sc + bb.z, 0.f);
    float hw = fmaxf(acc.w * sc + bb.w, 0.f);

    float un = (mode < 2) ? ns[n] : 1.0f;
    __half2 p0 = __floats2half2_rn(hx * un, hy * un);
    __half2 p1 = __floats2half2_rn(hz * un, hw * un);
    uint2 uu;
    uu.x = *(uint32_t*)&p0;
    uu.y = *(uint32_t*)&p1;
    ((uint2*)u)[(size_t)n * 32 + lane] = uu;
}

// ---------------- output zero init ----------------
__global__ void zero_out_kernel(float* out, int n) {
    int i = blockIdx.x * blockDim.x + threadIdx.x;
    if (i < n) out[i] = 0.f;
}

// ---------------- pooling: warp-per-node-range, no barriers ----------------
#define POOL_BLOCKS 400
#define POOL_TPB 256
__global__ void pool_kernel(const __half* __restrict__ h,
                            const int* __restrict__ gid,
                            const float* __restrict__ Wp,
                            const float* __restrict__ bp,
                            float* __restrict__ out, int N) {
    int gw = (blockIdx.x * POOL_TPB + threadIdx.x) >> 5;
    int lane = threadIdx.x & 31;
    const int nwarps = POOL_BLOCKS * (POOL_TPB / 32);
    int per = (N + nwarps - 1) / nwarps;
    int n0 = gw * per;
    if (n0 >= N) return;
    int n1 = n0 + per; if (n1 > N) n1 = N;

    float4 wp = ((const float4*)Wp)[lane];
    float bpv = bp[0];

    int gcur = __ldg(&gid[n0]);
    float4 ls = make_float4(0.f, 0.f, 0.f, 0.f);
    float4 lm = make_float4(0.f, 0.f, 0.f, 0.f);
    const uint2* h2 = (const uint2*)h;

    for (int n = n0; n < n1; n++) {
        int g = __ldg(&gid[n]);
        if (g != gcur) {
            float* os = &out[gcur * 2 * HDIM + lane * 4];
            float* om = os + HDIM;
            atomicAdd(&os[0], ls.x); atomicAdd(&os[1], ls.y);
            atomicAdd(&os[2], ls.z); atomicAdd(&os[3], ls.w);
            atomicMax((int*)&om[0], __float_as_int(lm.x));
            atomicMax((int*)&om[1], __float_as_int(lm.y));
            atomicMax((int*)&om[2], __float_as_int(lm.z));
            atomicMax((int*)&om[3], __float_as_int(lm.w));
            ls = make_float4(0.f, 0.f, 0.f, 0.f);
            lm = make_float4(0.f, 0.f, 0.f, 0.f);
            gcur = g;
        }
        float4 v = ldY4(h2, n, lane);
        float p = v.x * wp.x + v.y * wp.y + v.z * wp.z + v.w * wp.w;
        #pragma unroll
        for (int o = 16; o > 0; o >>= 1)
            p += __shfl_xor_sync(0xFFFFFFFFu, p, o);
        float w = 1.0f / (1.0f + expf(-(p + bpv)));
        ls.x += v.x * w; ls.y += v.y * w; ls.z += v.z * w; ls.w += v.w * w;
        lm.x = fmaxf(lm.x, v.x); lm.y = fmaxf(lm.y, v.y);
        lm.z = fmaxf(lm.z, v.z); lm.w = fmaxf(lm.w, v.w);
    }
    float* os = &out[gcur * 2 * HDIM + lane * 4];
    float* om = os + HDIM;
    atomicAdd(&os[0], ls.x); atomicAdd(&os[1], ls.y);
    atomicAdd(&os[2], ls.z); atomicAdd(&os[3], ls.w);
    atomicMax((int*)&om[0], __float_as_int(lm.x));
    atomicMax((int*)&om[1], __float_as_int(lm.y));
    atomicMax((int*)&om[2], __float_as_int(lm.z));
    atomicMax((int*)&om[3], __float_as_int(lm.w));
}

// ---------------- launch ----------------
extern "C" void kernel_launch(void* const* d_in, const int* in_sizes, int n_in,
                              void* d_out, int out_size) {
    const float* node_feats = (const float*)d_in[0];
    const int*   src        = (const int*)d_in[1];
    const int*   dst        = (const int*)d_in[2];
    const int*   gid        = (const int*)d_in[3];
    const float* W1 = (const float*)d_in[4];  const float* b1 = (const float*)d_in[5];
    const float* W2 = (const float*)d_in[6];  const float* b2 = (const float*)d_in[7];
    const float* W3 = (const float*)d_in[8];  const float* b3 = (const float*)d_in[9];
    const float* Wp = (const float*)d_in[10]; const float* bp = (const float*)d_in[11];
    float* out = (float*)d_out;

    const int N = in_sizes[0] / HDIM;
    const int E = in_sizes[1];

    float *pns, *pnd;
    __half *pYa, *pYb, *pu;
    __nv_bfloat16 *pWhi, *pWlo;
    int *pod, *pid_, *poff, *pcur, *pcsr, *pbs;
    cudaGetSymbolAddress((void**)&pYa,  g_Ya);
    cudaGetSymbolAddress((void**)&pYb,  g_Yb);
    cudaGetSymbolAddress((void**)&pu,   g_u);
    cudaGetSymbolAddress((void**)&pWhi, g_Whi);
    cudaGetSymbolAddress((void**)&pWlo, g_Wlo);
    cudaGetSymbolAddress((void**)&pns, g_ns);
    cudaGetSymbolAddress((void**)&pnd, g_nd);
    cudaGetSymbolAddress((void**)&pod, g_odeg);
    cudaGetSymbolAddress((void**)&pid_, g_ideg);
    cudaGetSymbolAddress((void**)&poff, g_off);
    cudaGetSymbolAddress((void**)&pcur, g_cursor);
    cudaGetSymbolAddress((void**)&pcsr, g_csr_src);
    cudaGetSymbolAddress((void**)&pbs, g_bsums);

    cudaFuncSetAttribute(mma_gemm_kernel,
                         cudaFuncAttributeMaxDynamicSharedMemorySize, SMEM_MMA);

    const int nblk_scan = (N + SCAN_BLK - 1) / SCAN_BLK;
    const int gemm_grid = (N + 127) / 128;

    // chunking (128-aligned first half)
    int C = (gemm_grid / 2) * 128;
    if (C <= 0 || C >= N) C = N;   // degenerate -> serial
    const int grid_c0 = (C + 127) / 128;
    const int grid_c1 = (N - C + 127) / 128;
    const int gb_c0 = (int)(((long long)C * 32 + 255) / 256);
    const int gb_c1 = (int)(((long long)(N - C) * 32 + 255) / 256);
    const int gb_full = (int)(((long long)N * 32 + 255) / 256);

    // --- streams/events: ONE side stream (proven), 4 events ---
    cudaStream_t sB;
    cudaStreamCreateWithFlags(&sB, cudaStreamNonBlocking);
    cudaEvent_t evFork, evJoin, evA, evB;
    cudaEventCreateWithFlags(&evFork, cudaEventDisableTiming);
    cudaEventCreateWithFlags(&evJoin, cudaEventDisableTiming);
    cudaEventCreateWithFlags(&evA,    cudaEventDisableTiming);
    cudaEventCreateWithFlags(&evB,    cudaEventDisableTiming);

    cudaEventRecord(evFork, 0);
    cudaStreamWaitEvent(sB, evFork, 0);

    // side stream: degrees/norms/CSR/zero-out
    zero_deg_kernel<<<(N + 255) / 256, 256, 0, sB>>>(pod, pid_, N);
    count_deg_kernel<<<(E + 255) / 256, 256, 0, sB>>>(src, dst, pod, pid_, E);
    norms_kernel<<<(N + 255) / 256, 256, 0, sB>>>(pod, pid_, pns, pnd, N);
    blocksum_kernel<<<nblk_scan, SCAN_BLK, 0, sB>>>(pid_, pbs, N);
    scan_bsums_kernel<<<1, MAX_BLKS, 0, sB>>>(pbs, nblk_scan);
    write_offsets_kernel<<<nblk_scan, SCAN_BLK, 0, sB>>>(pid_, pbs, poff, pcur, N);
    fill_csr_kernel<<<(E + 255) / 256, 256, 0, sB>>>(src, dst, pcur, pcsr, E);
    zero_out_kernel<<<(out_size + 255) / 256, 256, 0, sB>>>(out, out_size);
    cudaEventRecord(evJoin, sB);

    // main: conversions + GEMM1 (independent of norms/CSR)
    convertW_kernel<<<(3 * HDIM * HDIM + 255) / 256, 256>>>(W1, W2, W3, pWhi, pWlo);
    convertX_kernel<<<(N * 32 + 255) / 256, 256>>>(node_feats, pu, N * 32);
    mma_gemm_kernel<<<gemm_grid, 512, SMEM_MMA>>>(pu, pWhi, pWlo, pYa, 0, N);

    cudaStreamWaitEvent(0, evJoin, 0);   // gathers need CSR; sB now idle

    if (C < N) {
        // ---- layer 1: gather Ya -> u ; GEMM2 -> Yb (pipelined) ----
        gather_kernel<<<gb_c0, 256>>>(pYa, poff, pid_, pcsr, pns, pnd, b1,
                                      pu, 0, 0, C);
        cudaEventRecord(evA, 0);
        gather_kernel<<<gb_c1, 256>>>(pYa, poff, pid_, pcsr, pns, pnd, b1,
                                      pu, 0, C, N);
        cudaStreamWaitEvent(sB, evA, 0);
        mma_gemm_kernel<<<grid_c0, 512, SMEM_MMA, sB>>>(pu,
            pWhi + HDIM * HDIM, pWlo + HDIM * HDIM, pYb, 0, N);
        cudaEventRecord(evB, sB);
        cudaStreamWaitEvent(0, evB, 0);
        mma_gemm_kernel<<<grid_c1, 512, SMEM_MMA>>>(pu,
            pWhi + HDIM * HDIM, pWlo + HDIM * HDIM, pYb, C, N);

        // ---- layer 2: gather Yb -> u ; GEMM3 -> Ya (pipelined) ----
        gather_kernel<<<gb_c0, 256>>>(pYb, poff, pid_, pcsr, pns, pnd, b2,
                                      pu, 1, 0, C);
        cudaEventRecord(evA, 0);
        gather_kernel<<<gb_c1, 256>>>(pYb, poff, pid_, pcsr, pns, pnd, b2,
                                      pu, 1, C, N);
        cudaStreamWaitEvent(sB, evA, 0);
        mma_gemm_kernel<<<grid_c0, 512, SMEM_MMA, sB>>>(pu,
            pWhi + 2 * HDIM * HDIM, pWlo + 2 * HDIM * HDIM, pYa, 0, N);
        cudaEventRecord(evB, sB);
        cudaStreamWaitEvent(0, evB, 0);
        mma_gemm_kernel<<<grid_c1, 512, SMEM_MMA>>>(pu,
            pWhi + 2 * HDIM * HDIM, pWlo + 2 * HDIM * HDIM, pYa, C, N);
    } else {
        gather_kernel<<<gb_full, 256>>>(pYa, poff, pid_, pcsr, pns, pnd, b1,
                                        pu, 0, 0, N);
        mma_gemm_kernel<<<gemm_grid, 512, SMEM_MMA>>>(pu,
            pWhi + HDIM * HDIM, pWlo + HDIM * HDIM, pYb, 0, N);
        gather_kernel<<<gb_full, 256>>>(pYb, poff, pid_, pcsr, pns, pnd, b2,
                                        pu, 1, 0, N);
        mma_gemm_kernel<<<gemm_grid, 512, SMEM_MMA>>>(pu,
            pWhi + 2 * HDIM * HDIM, pWlo + 2 * HDIM * HDIM, pYa, 0, N);
    }

    // ---- final gather (fp16 h) + pool ----
    gather_kernel<<<gb_full, 256>>>(pYa, poff, pid_, pcsr, pns, pnd, b3,
                                    pu, 2, 0, N);
    pool_kernel<<<POOL_BLOCKS, POOL_TPB>>>(pu, gid, Wp, bp, out, N);
    // single side stream + 4 events, not destroyed (capture safety)
}

// round 16
// speedup vs baseline: 1.2742x; 1.2742x over previous
#include <cuda_runtime.h>
#include <cuda_fp16.h>
#include <mma.h>
#include <math.h>
#include <stdint.h>

using namespace nvcuda;

#define HDIM 128
#define MAXN 100000
#define MAXE 1600000
#define NUM_GRAPHS 100
#define SCAN_BLK 256
#define MAX_BLKS 512

// smem layout (bytes). ldm = 136 halves (272B rows)
#define LDA 136
#define SA   0
#define SB_HI (128 * LDA * 2)
#define SB_LO (2 * 128 * LDA * 2)
#define SMEM_MMA (3 * 128 * LDA * 2)   // 104448 bytes

// ---------------- scratch (no allocation allowed) ----------------
__device__ __half g_Y[MAXN * HDIM];            // Z (GEMM output, fp16)
__device__ __half g_u[MAXN * HDIM];            // u = ns*h / final h (fp16)
__device__ __half g_Whi[3 * HDIM * HDIM];      // W hi  [k][n] fp16
__device__ __half g_Wlo[3 * HDIM * HDIM];      // W lo  [k][n] fp16
__device__ float g_ns[MAXN];
__device__ float g_nd[MAXN];
__device__ int   g_odeg[MAXN];
__device__ int   g_ideg[MAXN];
__device__ int   g_off[MAXN];
__device__ int   g_cursor[MAXN];
__device__ int   g_csr_src[MAXE];
__device__ int   g_bsums[MAX_BLKS];

// ---------------- degree counting ----------------
__global__ void zero_deg_kernel(int* odeg, int* ideg, int N) {
    int i = blockIdx.x * blockDim.x + threadIdx.x;
    if (i < N) { odeg[i] = 0; ideg[i] = 0; }
}

__global__ void count_deg_kernel(const int* __restrict__ src,
                                 const int* __restrict__ dst,
                                 int* odeg, int* ideg, int E) {
    int i = blockIdx.x * blockDim.x + threadIdx.x;
    if (i < E) {
        atomicAdd(&odeg[src[i]], 1);
        atomicAdd(&ideg[dst[i]], 1);
    }
}

__global__ void norms_kernel(const int* __restrict__ odeg,
                             const int* __restrict__ ideg,
                             float* ns, float* nd, int N) {
    int i = blockIdx.x * blockDim.x + threadIdx.x;
    if (i < N) {
        ns[i] = rsqrtf((float)(odeg[i] + 1));
        nd[i] = rsqrtf((float)(ideg[i] + 1));
    }
}

// ---------------- prefix sum ----------------
__global__ void blocksum_kernel(const int* __restrict__ deg, int* bsums, int N) {
    __shared__ int s[SCAN_BLK];
    int i = blockIdx.x * SCAN_BLK + threadIdx.x;
    s[threadIdx.x] = (i < N) ? deg[i] : 0;
    __syncthreads();
    for (int o = SCAN_BLK / 2; o > 0; o >>= 1) {
        if (threadIdx.x < o) s[threadIdx.x] += s[threadIdx.x + o];
        __syncthreads();
    }
    if (threadIdx.x == 0) bsums[blockIdx.x] = s[0];
}

__global__ void scan_bsums_kernel(int* bsums, int nblk) {
    __shared__ int s[MAX_BLKS];
    int t = threadIdx.x;
    int v = (t < nblk) ? bsums[t] : 0;
    s[t] = v;
    __syncthreads();
    for (int o = 1; o < MAX_BLKS; o <<= 1) {
        int add = (t >= o) ? s[t - o] : 0;
        __syncthreads();
        s[t] += add;
        __syncthreads();
    }
    if (t < nblk) bsums[t] = s[t] - v;
}

__global__ void write_offsets_kernel(const int* __restrict__ deg,
                                     const int* __restrict__ bsums,
                                     int* off, int* cursor, int N) {
    __shared__ int s[SCAN_BLK];
    int i = blockIdx.x * SCAN_BLK + threadIdx.x;
    int t = threadIdx.x;
    int v = (i < N) ? deg[i] : 0;
    s[t] = v;
    __syncthreads();
    for (int o = 1; o < SCAN_BLK; o <<= 1) {
        int add = (t >= o) ? s[t - o] : 0;
        __syncthreads();
        s[t] += add;
        __syncthreads();
    }
    if (i < N) {
        int ofs = bsums[blockIdx.x] + s[t] - v;
        off[i] = ofs;
        cursor[i] = ofs;
    }
}

__global__ void fill_csr_kernel(const int* __restrict__ src,
                                const int* __restrict__ dst,
                                int* cursor, int* csr_src, int E) {
    int i = blockIdx.x * blockDim.x + threadIdx.x;
    if (i < E) {
        int slot = atomicAdd(&cursor[dst[i]], 1);
        csr_src[slot] = src[i];
    }
}

// ---------------- convert W: fp16 hi/lo split ----------------
__global__ void convertW_kernel(const float* __restrict__ W1,
                                const float* __restrict__ W2,
                                const float* __restrict__ W3,
                                __half* __restrict__ Whi,
                                __half* __restrict__ Wlo) {
    int i = blockIdx.x * blockDim.x + threadIdx.x;
    if (i >= 3 * HDIM * HDIM) return;
    int w = i / (HDIM * HDIM);
    int r = i % (HDIM * HDIM);
    const float* W = (w == 0) ? W1 : ((w == 1) ? W2 : W3);
    float v = W[r];
    __half hi = __float2half_rn(v);
    Whi[i] = hi;
    Wlo[i] = __float2half_rn(v - __half2float(hi));
}

// ---------------- convert X (fp32 -> fp16) ----------------
__global__ void convertX_kernel(const float* __restrict__ X,
                                __half* __restrict__ Xh, int n4) {
    int i = blockIdx.x * blockDim.x + threadIdx.x;
    if (i >= n4) return;
    float4 v = ((const float4*)X)[i];
    __half2 p0 = __floats2half2_rn(v.x, v.y);
    __half2 p1 = __floats2half2_rn(v.z, v.w);
    uint2 u;
    u.x = *(uint32_t*)&p0;
    u.y = *(uint32_t*)&p1;
    ((uint2*)Xh)[i] = u;
}

// ---------------- pure-fp16 wmma GEMM, 2-term W split -----------------
// Z[m][n] = sum_k A[m][k]*(Whi+Wlo)[k][n], fp32 accum. A fp16 exact.
// CTA: 128x128 tile, 512 threads = 16 warps (4x4), warp tile 32x32.
__global__ void __launch_bounds__(512)
mma_gemm_kernel(const __half* __restrict__ A,
                const __half* __restrict__ Whi,
                const __half* __restrict__ Wlo,
                __half* __restrict__ Y, int N) {
    extern __shared__ char smem[];
    __half* sA   = (__half*)(smem + SA);
    __half* sBhi = (__half*)(smem + SB_HI);
    __half* sBlo = (__half*)(smem + SB_LO);

    const int tid = threadIdx.x;
    const int base = blockIdx.x * 128;

    const uint4* WH4 = (const uint4*)Whi;
    const uint4* WL4 = (const uint4*)Wlo;
    const uint4* A4 = (const uint4*)A;
    const uint4 z4 = make_uint4(0, 0, 0, 0);
    #pragma unroll
    for (int i = tid; i < 128 * 16; i += 512) {
        int row = i >> 4, c8 = i & 15;
        int gr = base + row;
        *(uint4*)&sA[row * LDA + c8 * 8]   = (gr < N) ? A4[(size_t)gr * 16 + c8] : z4;
        *(uint4*)&sBhi[row * LDA + c8 * 8] = WH4[i];
        *(uint4*)&sBlo[row * LDA + c8 * 8] = WL4[i];
    }
    __syncthreads();

    const int wid = tid >> 5;
    const int wm = wid & 3;
    const int wn = wid >> 2;

    wmma::fragment<wmma::accumulator, 16, 16, 16, float> acc[2][2];
    #pragma unroll
    for (int i = 0; i < 2; i++)
        #pragma unroll
        for (int j = 0; j < 2; j++)
            wmma::fill_fragment(acc[i][j], 0.0f);

    #pragma unroll
    for (int ks = 0; ks < 8; ks++) {
        wmma::fragment<wmma::matrix_a, 16, 16, 16, __half, wmma::row_major> a[2];
        wmma::fragment<wmma::matrix_b, 16, 16, 16, __half, wmma::row_major> bhi[2], blo[2];
        #pragma unroll
        for (int i = 0; i < 2; i++)
            wmma::load_matrix_sync(a[i], &sA[(wm * 32 + i * 16) * LDA + ks * 16], LDA);
        #pragma unroll
        for (int j = 0; j < 2; j++) {
            wmma::load_matrix_sync(bhi[j], &sBhi[(ks * 16) * LDA + wn * 32 + j * 16], LDA);
            wmma::load_matrix_sync(blo[j], &sBlo[(ks * 16) * LDA + wn * 32 + j * 16], LDA);
        }
        #pragma unroll
        for (int i = 0; i < 2; i++)
            #pragma unroll
            for (int j = 0; j < 2; j++) {
                wmma::mma_sync(acc[i][j], a[i], bhi[j], acc[i][j]);
                wmma::mma_sync(acc[i][j], a[i], blo[j], acc[i][j]);
            }
    }

    __syncthreads();
    float* fs = (float*)smem;   // 64 KB staging (aliases sA/sBhi; wmma loads done)
    #pragma unroll
    for (int i = 0; i < 2; i++)
        #pragma unroll
        for (int j = 0; j < 2; j++)
            wmma::store_matrix_sync(
                fs + (wm * 32 + i * 16) * HDIM + wn * 32 + j * 16,
                acc[i][j], HDIM, wmma::mem_row_major);
    __syncthreads();
    uint2* Y2 = (uint2*)Y;
    const float4* fs4 = (const float4*)fs;
    #pragma unroll
    for (int i = tid; i < 128 * 32; i += 512) {
        int row = i >> 5;
        int gr = base + row;
        if (gr < N) {
            float4 v = fs4[i];
            __half2 p0 = __floats2half2_rn(v.x, v.y);
            __half2 p1 = __floats2half2_rn(v.z, v.w);
            uint2 u;
            u.x = *(uint32_t*)&p0;
            u.y = *(uint32_t*)&p1;
            Y2[(size_t)gr * 32 + (i & 31)] = u;
        }
    }
}

// ---------------- fp16 row-chunk load: 4 dims per lane ----------------
__device__ __forceinline__ float4 ldY4(const uint2* __restrict__ Y2,
                                       int n, int lane) {
    uint2 u = __ldg(&Y2[(size_t)n * 32 + lane]);
    __half2 a = *(__half2*)&u.x;
    __half2 b = *(__half2*)&u.y;
    float2 fa = __half22float2(a);
    float2 fb = __half22float2(b);
    return make_float4(fa.x, fa.y, fb.x, fb.y);
}

// ---------------- fused gather + epilogue + next-layer input prep ----------
// mode 0: per-edge ns (layer 1), out u = ns*h fp16
// mode 1: pre-scaled input, out u = ns*h fp16
// mode 2: pre-scaled input, out h fp16 (final, for pool)
__global__ void gather_kernel(const __half* __restrict__ Z,
                              const int* __restrict__ off,
                              const int* __restrict__ ideg,
                              const int* __restrict__ csr_src,
                              const float* __restrict__ ns,
                              const float* __restrict__ nd,
                              const float* __restrict__ b,
                              __half* __restrict__ u,
                              int mode, int N) {
    int gt = blockIdx.x * blockDim.x + threadIdx.x;
    int n = gt >> 5;
    int lane = threadIdx.x & 31;
    if (n >= N) return;

    const uint2* Z2 = (const uint2*)Z;
    float4 acc = ldY4(Z2, n, lane);
    if (mode == 0) {
        float sn = ns[n];
        acc.x *= sn; acc.y *= sn; acc.z *= sn; acc.w *= sn;
    }
    int o = off[n];
    int d = ideg[n];

    int e = 0;
    if (mode == 0) {
        for (; e + 4 <= d; e += 4) {
            int s0 = csr_src[o + e + 0];
            int s1 = csr_src[o + e + 1];
            int s2 = csr_src[o + e + 2];
            int s3 = csr_src[o + e + 3];
            float n0 = __ldg(&ns[s0]);
            float n1 = __ldg(&ns[s1]);
            float n2 = __ldg(&ns[s2]);
            float n3 = __ldg(&ns[s3]);
            float4 v0 = ldY4(Z2, s0, lane);
            float4 v1 = ldY4(Z2, s1, lane);
            float4 v2 = ldY4(Z2, s2, lane);
            float4 v3 = ldY4(Z2, s3, lane);
            acc.x += v0.x * n0 + v1.x * n1 + v2.x * n2 + v3.x * n3;
            acc.y += v0.y * n0 + v1.y * n1 + v2.y * n2 + v3.y * n3;
            acc.z += v0.z * n0 + v1.z * n1 + v2.z * n2 + v3.z * n3;
            acc.w += v0.w * n0 + v1.w * n1 + v2.w * n2 + v3.w * n3;
        }
        for (; e < d; e++) {
            int s = csr_src[o + e];
            float nn = __ldg(&ns[s]);
            float4 v = ldY4(Z2, s, lane);
            acc.x += v.x * nn; acc.y += v.y * nn;
            acc.z += v.z * nn; acc.w += v.w * nn;
        }
    } else {
        for (; e + 4 <= d; e += 4) {
            int s0 = csr_src[o + e + 0];
            int s1 = csr_src[o + e + 1];
            int s2 = csr_src[o + e + 2];
            int s3 = csr_src[o + e + 3];
            float4 v0 = ldY4(Z2, s0, lane);
            float4 v1 = ldY4(Z2, s1, lane);
            float4 v2 = ldY4(Z2, s2, lane);
            float4 v3 = ldY4(Z2, s3, lane);
            acc.x += v0.x + v1.x + v2.x + v3.x;
            acc.y += v0.y + v1.y + v2.y + v3.y;
            acc.z += v0.z + v1.z + v2.z + v3.z;
            acc.w += v0.w + v1.w + v2.w + v3.w;
        }
        for (; e < d; e++) {
            int s = csr_src[o + e];
            float4 v = ldY4(Z2, s, lane);
            acc.x += v.x; acc.y += v.y; acc.z += v.z; acc.w += v.w;
        }
    }

    float sc = nd[n];
    float4 bb = ((const float4*)b)[lane];
    float hx = fmaxf(acc.x * sc + bb.x, 0.f);
    float hy = fmaxf(acc.y * sc + bb.y, 0.f);
    float hz = fmaxf(acc.z * sc + bb.z, 0.f);
    float hw = fmaxf(acc.w * sc + bb.w, 0.f);

    float un = (mode < 2) ? ns[n] : 1.0f;
    __half2 p0 = __floats2half2_rn(hx * un, hy * un);
    __half2 p1 = __floats2half2_rn(hz * un, hw * un);
    uint2 uu;
    uu.x = *(uint32_t*)&p0;
    uu.y = *(uint32_t*)&p1;
    ((uint2*)u)[(size_t)n * 32 + lane] = uu;
}

// ---------------- output zero init ----------------
__global__ void zero_out_kernel(float* out, int n) {
    int i = blockIdx.x * blockDim.x + threadIdx.x;
    if (i < n) out[i] = 0.f;
}

// ---------------- pooling: warp-per-node-range, no barriers ----------------
#define POOL_BLOCKS 400
#define POOL_TPB 256
__global__ void pool_kernel(const __half* __restrict__ h,
                            const int* __restrict__ gid,
                            const float* __restrict__ Wp,
                            const float* __restrict__ bp,
                            float* __restrict__ out, int N) {
    int gw = (blockIdx.x * POOL_TPB + threadIdx.x) >> 5;
    int lane = threadIdx.x & 31;
    const int nwarps = POOL_BLOCKS * (POOL_TPB / 32);
    int per = (N + nwarps - 1) / nwarps;
    int n0 = gw * per;
    if (n0 >= N) return;
    int n1 = n0 + per; if (n1 > N) n1 = N;

    float4 wp = ((const float4*)Wp)[lane];
    float bpv = bp[0];

    int gcur = __ldg(&gid[n0]);
    float4 ls = make_float4(0.f, 0.f, 0.f, 0.f);
    float4 lm = make_float4(0.f, 0.f, 0.f, 0.f);
    const uint2* h2 = (const uint2*)h;

    for (int n = n0; n < n1; n++) {
        int g = __ldg(&gid[n]);
        if (g != gcur) {
            float* os = &out[gcur * 2 * HDIM + lane * 4];
            float* om = os + HDIM;
            atomicAdd(&os[0], ls.x); atomicAdd(&os[1], ls.y);
            atomicAdd(&os[2], ls.z); atomicAdd(&os[3], ls.w);
            atomicMax((int*)&om[0], __float_as_int(lm.x));
            atomicMax((int*)&om[1], __float_as_int(lm.y));
            atomicMax((int*)&om[2], __float_as_int(lm.z));
            atomicMax((int*)&om[3], __float_as_int(lm.w));
            ls = make_float4(0.f, 0.f, 0.f, 0.f);
            lm = make_float4(0.f, 0.f, 0.f, 0.f);
            gcur = g;
        }
        float4 v = ldY4(h2, n, lane);
        float p = v.x * wp.x + v.y * wp.y + v.z * wp.z + v.w * wp.w;
        #pragma unroll
        for (int o = 16; o > 0; o >>= 1)
            p += __shfl_xor_sync(0xFFFFFFFFu, p, o);
        float w = 1.0f / (1.0f + expf(-(p + bpv)));
        ls.x += v.x * w; ls.y += v.y * w; ls.z += v.z * w; ls.w += v.w * w;
        lm.x = fmaxf(lm.x, v.x); lm.y = fmaxf(lm.y, v.y);
        lm.z = fmaxf(lm.z, v.z); lm.w = fmaxf(lm.w, v.w);
    }
    float* os = &out[gcur * 2 * HDIM + lane * 4];
    float* om = os + HDIM;
    atomicAdd(&os[0], ls.x); atomicAdd(&os[1], ls.y);
    atomicAdd(&os[2], ls.z); atomicAdd(&os[3], ls.w);
    atomicMax((int*)&om[0], __float_as_int(lm.x));
    atomicMax((int*)&om[1], __float_as_int(lm.y));
    atomicMax((int*)&om[2], __float_as_int(lm.z));
    atomicMax((int*)&om[3], __float_as_int(lm.w));
}

// ---------------- launch ----------------
extern "C" void kernel_launch(void* const* d_in, const int* in_sizes, int n_in,
                              void* d_out, int out_size) {
    const float* node_feats = (const float*)d_in[0];
    const int*   src        = (const int*)d_in[1];
    const int*   dst        = (const int*)d_in[2];
    const int*   gid        = (const int*)d_in[3];
    const float* W1 = (const float*)d_in[4];  const float* b1 = (const float*)d_in[5];
    const float* W2 = (const float*)d_in[6];  const float* b2 = (const float*)d_in[7];
    const float* W3 = (const float*)d_in[8];  const float* b3 = (const float*)d_in[9];
    const float* Wp = (const float*)d_in[10]; const float* bp = (const float*)d_in[11];
    float* out = (float*)d_out;

    const int N = in_sizes[0] / HDIM;
    const int E = in_sizes[1];

    float *pns, *pnd;
    __half *pY, *pu, *pWhi, *pWlo;
    int *pod, *pid_, *poff, *pcur, *pcsr, *pbs;
    cudaGetSymbolAddress((void**)&pY,   g_Y);
    cudaGetSymbolAddress((void**)&pu,   g_u);
    cudaGetSymbolAddress((void**)&pWhi, g_Whi);
    cudaGetSymbolAddress((void**)&pWlo, g_Wlo);
    cudaGetSymbolAddress((void**)&pns, g_ns);
    cudaGetSymbolAddress((void**)&pnd, g_nd);
    cudaGetSymbolAddress((void**)&pod, g_odeg);
    cudaGetSymbolAddress((void**)&pid_, g_ideg);
    cudaGetSymbolAddress((void**)&poff, g_off);
    cudaGetSymbolAddress((void**)&pcur, g_cursor);
    cudaGetSymbolAddress((void**)&pcsr, g_csr_src);
    cudaGetSymbolAddress((void**)&pbs, g_bsums);

    cudaFuncSetAttribute(mma_gemm_kernel,
                         cudaFuncAttributeMaxDynamicSharedMemorySize, SMEM_MMA);

    const int nblk_scan = (N + SCAN_BLK - 1) / SCAN_BLK;
    const int gemm_grid = (N + 127) / 128;
    const int gather_blocks = (int)(((long long)N * 32 + 255) / 256);

    // --- fork: CSR/norm build on side stream; conversions + GEMM1 on main ---
    cudaStream_t sB;
    cudaStreamCreateWithFlags(&sB, cudaStreamNonBlocking);
    cudaEvent_t evFork, evJoin;
    cudaEventCreateWithFlags(&evFork, cudaEventDisableTiming);
    cudaEventCreateWithFlags(&evJoin, cudaEventDisableTiming);

    cudaEventRecord(evFork, 0);
    cudaStreamWaitEvent(sB, evFork, 0);

    zero_deg_kernel<<<(N + 255) / 256, 256, 0, sB>>>(pod, pid_, N);
    count_deg_kernel<<<(E + 255) / 256, 256, 0, sB>>>(src, dst, pod, pid_, E);
    norms_kernel<<<(N + 255) / 256, 256, 0, sB>>>(pod, pid_, pns, pnd, N);
    blocksum_kernel<<<nblk_scan, SCAN_BLK, 0, sB>>>(pid_, pbs, N);
    scan_bsums_kernel<<<1, MAX_BLKS, 0, sB>>>(pbs, nblk_scan);
    write_offsets_kernel<<<nblk_scan, SCAN_BLK, 0, sB>>>(pid_, pbs, poff, pcur, N);
    fill_csr_kernel<<<(E + 255) / 256, 256, 0, sB>>>(src, dst, pcur, pcsr, E);
    zero_out_kernel<<<(out_size + 255) / 256, 256, 0, sB>>>(out, out_size);

    // main: W + X conversion, GEMM1 (independent of norms/CSR)
    convertW_kernel<<<(3 * HDIM * HDIM + 255) / 256, 256>>>(W1, W2, W3, pWhi, pWlo);
    convertX_kernel<<<(N * 32 + 255) / 256, 256>>>(node_feats, pu, N * 32);
    mma_gemm_kernel<<<gemm_grid, 512, SMEM_MMA>>>(pu, pWhi, pWlo, pY, N);

    cudaEventRecord(evJoin, sB);
    cudaStreamWaitEvent(0, evJoin, 0);

    // --- layer 1 gather (per-edge ns), then layers 2-3 (serial; overlap loses) ---
    gather_kernel<<<gather_blocks, 256>>>(pY, poff, pid_, pcsr, pns, pnd, b1,
                                          pu, 0, N);
    mma_gemm_kernel<<<gemm_grid, 512, SMEM_MMA>>>(pu,
                                                  pWhi + HDIM * HDIM,
                                                  pWlo + HDIM * HDIM, pY, N);
    gather_kernel<<<gather_blocks, 256>>>(pY, poff, pid_, pcsr, pns, pnd, b2,
                                          pu, 1, N);
    mma_gemm_kernel<<<gemm_grid, 512, SMEM_MMA>>>(pu,
                                                  pWhi + 2 * HDIM * HDIM,
                                                  pWlo + 2 * HDIM * HDIM, pY, N);
    gather_kernel<<<gather_blocks, 256>>>(pY, poff, pid_, pcsr, pns, pnd, b3,
                                          pu, 2, N);

    pool_kernel<<<POOL_BLOCKS, POOL_TPB>>>(pu, gid, Wp, bp, out, N);
    // single side stream + 2 events, not destroyed (round-6-proven pattern)
}

// round 17
// speedup vs baseline: 1.3668x; 1.0726x over previous
#include <cuda_runtime.h>
#include <cuda_fp16.h>
#include <mma.h>
#include <math.h>
#include <stdint.h>

using namespace nvcuda;

#define HDIM 128
#define MAXN 100000
#define MAXE 1600000
#define NUM_GRAPHS 100
#define SCAN_BLK 256
#define MAX_BLKS 512

// smem layout (bytes). ldm = 136 halves (272B rows)
#define LDA 136
#define SA 0
#define SB (128 * LDA * 2)
#define SMEM_MMA (2 * 128 * LDA * 2)   // 69632 bytes -> 2 CTAs/SM

// ---------------- scratch (no allocation allowed) ----------------
__device__ __half g_Y[MAXN * HDIM];            // Z (GEMM output, fp16)
__device__ __half g_u[MAXN * HDIM];            // u = ns*h / final h (fp16)
__device__ __half g_W[3 * HDIM * HDIM];        // W [k][n] fp16
__device__ float g_ns[MAXN];
__device__ float g_nd[MAXN];
__device__ int   g_odeg[MAXN];
__device__ int   g_ideg[MAXN];
__device__ int   g_off[MAXN];
__device__ int   g_cursor[MAXN];
__device__ int   g_csr_src[MAXE];
__device__ int   g_bsums[MAX_BLKS];

// ---------------- degree counting ----------------
__global__ void count_deg_kernel(const int* __restrict__ src,
                                 const int* __restrict__ dst,
                                 int* odeg, int* ideg, int E) {
    int i = blockIdx.x * blockDim.x + threadIdx.x;
    if (i < E) {
        atomicAdd(&odeg[src[i]], 1);
        atomicAdd(&ideg[dst[i]], 1);
    }
}

__global__ void norms_kernel(const int* __restrict__ odeg,
                             const int* __restrict__ ideg,
                             float* ns, float* nd, int N) {
    int i = blockIdx.x * blockDim.x + threadIdx.x;
    if (i < N) {
        ns[i] = rsqrtf((float)(odeg[i] + 1));
        nd[i] = rsqrtf((float)(ideg[i] + 1));
    }
}

// ---------------- prefix sum ----------------
__global__ void blocksum_kernel(const int* __restrict__ deg, int* bsums, int N) {
    __shared__ int s[SCAN_BLK];
    int i = blockIdx.x * SCAN_BLK + threadIdx.x;
    s[threadIdx.x] = (i < N) ? deg[i] : 0;
    __syncthreads();
    for (int o = SCAN_BLK / 2; o > 0; o >>= 1) {
        if (threadIdx.x < o) s[threadIdx.x] += s[threadIdx.x + o];
        __syncthreads();
    }
    if (threadIdx.x == 0) bsums[blockIdx.x] = s[0];
}

__global__ void scan_bsums_kernel(int* bsums, int nblk) {
    __shared__ int s[MAX_BLKS];
    int t = threadIdx.x;
    int v = (t < nblk) ? bsums[t] : 0;
    s[t] = v;
    __syncthreads();
    for (int o = 1; o < MAX_BLKS; o <<= 1) {
        int add = (t >= o) ? s[t - o] : 0;
        __syncthreads();
        s[t] += add;
        __syncthreads();
    }
    if (t < nblk) bsums[t] = s[t] - v;
}

__global__ void write_offsets_kernel(const int* __restrict__ deg,
                                     const int* __restrict__ bsums,
                                     int* off, int* cursor, int N) {
    __shared__ int s[SCAN_BLK];
    int i = blockIdx.x * SCAN_BLK + threadIdx.x;
    int t = threadIdx.x;
    int v = (i < N) ? deg[i] : 0;
    s[t] = v;
    __syncthreads();
    for (int o = 1; o < SCAN_BLK; o <<= 1) {
        int add = (t >= o) ? s[t - o] : 0;
        __syncthreads();
        s[t] += add;
        __syncthreads();
    }
    if (i < N) {
        int ofs = bsums[blockIdx.x] + s[t] - v;
        off[i] = ofs;
        cursor[i] = ofs;
    }
}

__global__ void fill_csr_kernel(const int* __restrict__ src,
                                const int* __restrict__ dst,
                                int* cursor, int* csr_src, int E) {
    int i = blockIdx.x * blockDim.x + threadIdx.x;
    if (i < E) {
        int slot = atomicAdd(&cursor[dst[i]], 1);
        csr_src[slot] = src[i];
    }
}

// ---------------- convert W: fp32 -> fp16 ----------------
__global__ void convertW_kernel(const float* __restrict__ W1,
                                const float* __restrict__ W2,
                                const float* __restrict__ W3,
                                __half* __restrict__ W) {
    int i = blockIdx.x * blockDim.x + threadIdx.x;
    if (i >= 3 * HDIM * HDIM) return;
    int w = i / (HDIM * HDIM);
    int r = i % (HDIM * HDIM);
    const float* Ws = (w == 0) ? W1 : ((w == 1) ? W2 : W3);
    W[i] = __float2half_rn(Ws[r]);
}

// ---------------- convert X (fp32 -> fp16) ----------------
__global__ void convertX_kernel(const float* __restrict__ X,
                                __half* __restrict__ Xh, int n4) {
    int i = blockIdx.x * blockDim.x + threadIdx.x;
    if (i >= n4) return;
    float4 v = ((const float4*)X)[i];
    __half2 p0 = __floats2half2_rn(v.x, v.y);
    __half2 p1 = __floats2half2_rn(v.z, v.w);
    uint2 u;
    u.x = *(uint32_t*)&p0;
    u.y = *(uint32_t*)&p1;
    ((uint2*)Xh)[i] = u;
}

// ---------------- pure-fp16 wmma GEMM (single term) -------------------
// Z[m][n] = sum_k A[m][k]*W[k][n], fp32 accum.
// CTA: 128x128 tile, 512 threads = 16 warps (4x4), warp tile 32x32.
__global__ void __launch_bounds__(512)
mma_gemm_kernel(const __half* __restrict__ A,
                const __half* __restrict__ W,
                __half* __restrict__ Y, int N) {
    extern __shared__ char smem[];
    __half* sA = (__half*)(smem + SA);
    __half* sB = (__half*)(smem + SB);

    const int tid = threadIdx.x;
    const int base = blockIdx.x * 128;

    const uint4* W4 = (const uint4*)W;
    const uint4* A4 = (const uint4*)A;
    const uint4 z4 = make_uint4(0, 0, 0, 0);
    #pragma unroll
    for (int i = tid; i < 128 * 16; i += 512) {
        int row = i >> 4, c8 = i & 15;
        int gr = base + row;
        *(uint4*)&sA[row * LDA + c8 * 8] = (gr < N) ? A4[(size_t)gr * 16 + c8] : z4;
        *(uint4*)&sB[row * LDA + c8 * 8] = W4[i];
    }
    __syncthreads();

    const int wid = tid >> 5;
    const int wm = wid & 3;
    const int wn = wid >> 2;

    wmma::fragment<wmma::accumulator, 16, 16, 16, float> acc[2][2];
    #pragma unroll
    for (int i = 0; i < 2; i++)
        #pragma unroll
        for (int j = 0; j < 2; j++)
            wmma::fill_fragment(acc[i][j], 0.0f);

    #pragma unroll
    for (int ks = 0; ks < 8; ks++) {
        wmma::fragment<wmma::matrix_a, 16, 16, 16, __half, wmma::row_major> a[2];
        wmma::fragment<wmma::matrix_b, 16, 16, 16, __half, wmma::row_major> b[2];
        #pragma unroll
        for (int i = 0; i < 2; i++)
            wmma::load_matrix_sync(a[i], &sA[(wm * 32 + i * 16) * LDA + ks * 16], LDA);
        #pragma unroll
        for (int j = 0; j < 2; j++)
            wmma::load_matrix_sync(b[j], &sB[(ks * 16) * LDA + wn * 32 + j * 16], LDA);
        #pragma unroll
        for (int i = 0; i < 2; i++)
            #pragma unroll
            for (int j = 0; j < 2; j++)
                wmma::mma_sync(acc[i][j], a[i], b[j], acc[i][j]);
    }

    __syncthreads();
    float* fs = (float*)smem;   // 64 KB staging (aliases sA/sB; wmma loads done)
    #pragma unroll
    for (int i = 0; i < 2; i++)
        #pragma unroll
        for (int j = 0; j < 2; j++)
            wmma::store_matrix_sync(
                fs + (wm * 32 + i * 16) * HDIM + wn * 32 + j * 16,
                acc[i][j], HDIM, wmma::mem_row_major);
    __syncthreads();
    uint2* Y2 = (uint2*)Y;
    const float4* fs4 = (const float4*)fs;
    #pragma unroll
    for (int i = tid; i < 128 * 32; i += 512) {
        int row = i >> 5;
        int gr = base + row;
        if (gr < N) {
            float4 v = fs4[i];
            __half2 p0 = __floats2half2_rn(v.x, v.y);
            __half2 p1 = __floats2half2_rn(v.z, v.w);
            uint2 u;
            u.x = *(uint32_t*)&p0;
            u.y = *(uint32_t*)&p1;
            Y2[(size_t)gr * 32 + (i & 31)] = u;
        }
    }
}

// ---------------- fp16 row-chunk load: 4 dims per lane ----------------
__device__ __forceinline__ float4 ldY4(const uint2* __restrict__ Y2,
                                       int n, int lane) {
    uint2 u = __ldg(&Y2[(size_t)n * 32 + lane]);
    __half2 a = *(__half2*)&u.x;
    __half2 b = *(__half2*)&u.y;
    float2 fa = __half22float2(a);
    float2 fb = __half22float2(b);
    return make_float4(fa.x, fa.y, fb.x, fb.y);
}

// ---------------- fused gather + epilogue + next-layer input prep ----------
// mode 0: per-edge ns (layer 1), out u = ns*h fp16
// mode 1: pre-scaled input, out u = ns*h fp16
// mode 2: pre-scaled input, out h fp16 (final, for pool)
__global__ void gather_kernel(const __half* __restrict__ Z,
                              const int* __restrict__ off,
                              const int* __restrict__ ideg,
                              const int* __restrict__ csr_src,
                              const float* __restrict__ ns,
                              const float* __restrict__ nd,
                              const float* __restrict__ b,
                              __half* __restrict__ u,
                              int mode, int N) {
    int gt = blockIdx.x * blockDim.x + threadIdx.x;
    int n = gt >> 5;
    int lane = threadIdx.x & 31;
    if (n >= N) return;

    const uint2* Z2 = (const uint2*)Z;
    float4 acc = ldY4(Z2, n, lane);
    if (mode == 0) {
        float sn = ns[n];
        acc.x *= sn; acc.y *= sn; acc.z *= sn; acc.w *= sn;
    }
    int o = off[n];
    int d = ideg[n];

    int e = 0;
    if (mode == 0) {
        for (; e + 4 <= d; e += 4) {
            int s0 = csr_src[o + e + 0];
            int s1 = csr_src[o + e + 1];
            int s2 = csr_src[o + e + 2];
            int s3 = csr_src[o + e + 3];
            float n0 = __ldg(&ns[s0]);
            float n1 = __ldg(&ns[s1]);
            float n2 = __ldg(&ns[s2]);
            float n3 = __ldg(&ns[s3]);
            float4 v0 = ldY4(Z2, s0, lane);
            float4 v1 = ldY4(Z2, s1, lane);
            float4 v2 = ldY4(Z2, s2, lane);
            float4 v3 = ldY4(Z2, s3, lane);
            acc.x += v0.x * n0 + v1.x * n1 + v2.x * n2 + v3.x * n3;
            acc.y += v0.y * n0 + v1.y * n1 + v2.y * n2 + v3.y * n3;
            acc.z += v0.z * n0 + v1.z * n1 + v2.z * n2 + v3.z * n3;
            acc.w += v0.w * n0 + v1.w * n1 + v2.w * n2 + v3.w * n3;
        }
        for (; e < d; e++) {
            int s = csr_src[o + e];
            float nn = __ldg(&ns[s]);
            float4 v = ldY4(Z2, s, lane);
            acc.x += v.x * nn; acc.y += v.y * nn;
            acc.z += v.z * nn; acc.w += v.w * nn;
        }
    } else {
        for (; e + 4 <= d; e += 4) {
            int s0 = csr_src[o + e + 0];
            int s1 = csr_src[o + e + 1];
            int s2 = csr_src[o + e + 2];
            int s3 = csr_src[o + e + 3];
            float4 v0 = ldY4(Z2, s0, lane);
            float4 v1 = ldY4(Z2, s1, lane);
            float4 v2 = ldY4(Z2, s2, lane);
            float4 v3 = ldY4(Z2, s3, lane);
            acc.x += v0.x + v1.x + v2.x + v3.x;
            acc.y += v0.y + v1.y + v2.y + v3.y;
            acc.z += v0.z + v1.z + v2.z + v3.z;
            acc.w += v0.w + v1.w + v2.w + v3.w;
        }
        for (; e < d; e++) {
            int s = csr_src[o + e];
            float4 v = ldY4(Z2, s, lane);
            acc.x += v.x; acc.y += v.y; acc.z += v.z; acc.w += v.w;
        }
    }

    float sc = nd[n];
    float4 bb = ((const float4*)b)[lane];
    float hx = fmaxf(acc.x * sc + bb.x, 0.f);
    float hy = fmaxf(acc.y * sc + bb.y, 0.f);
    float hz = fmaxf(acc.z * sc + bb.z, 0.f);
    float hw = fmaxf(acc.w * sc + bb.w, 0.f);

    float un = (mode < 2) ? ns[n] : 1.0f;
    __half2 p0 = __floats2half2_rn(hx * un, hy * un);
    __half2 p1 = __floats2half2_rn(hz * un, hw * un);
    uint2 uu;
    uu.x = *(uint32_t*)&p0;
    uu.y = *(uint32_t*)&p1;
    ((uint2*)u)[(size_t)n * 32 + lane] = uu;
}

// ---------------- output zero init ----------------
__global__ void zero_out_kernel(float* out, int n) {
    int i = blockIdx.x * blockDim.x + threadIdx.x;
    if (i < n) out[i] = 0.f;
}

// ---------------- pooling: warp-per-node-range, no barriers ----------------
#define POOL_BLOCKS 400
#define POOL_TPB 256
__global__ void pool_kernel(const __half* __restrict__ h,
                            const int* __restrict__ gid,
                            const float* __restrict__ Wp,
                            const float* __restrict__ bp,
                            float* __restrict__ out, int N) {
    int gw = (blockIdx.x * POOL_TPB + threadIdx.x) >> 5;
    int lane = threadIdx.x & 31;
    const int nwarps = POOL_BLOCKS * (POOL_TPB / 32);
    int per = (N + nwarps - 1) / nwarps;
    int n0 = gw * per;
    if (n0 >= N) return;
    int n1 = n0 + per; if (n1 > N) n1 = N;

    float4 wp = ((const float4*)Wp)[lane];
    float bpv = bp[0];

    int gcur = __ldg(&gid[n0]);
    float4 ls = make_float4(0.f, 0.f, 0.f, 0.f);
    float4 lm = make_float4(0.f, 0.f, 0.f, 0.f);
    const uint2* h2 = (const uint2*)h;

    for (int n = n0; n < n1; n++) {
        int g = __ldg(&gid[n]);
        if (g != gcur) {
            float* os = &out[gcur * 2 * HDIM + lane * 4];
            float* om = os + HDIM;
            atomicAdd(&os[0], ls.x); atomicAdd(&os[1], ls.y);
            atomicAdd(&os[2], ls.z); atomicAdd(&os[3], ls.w);
            atomicMax((int*)&om[0], __float_as_int(lm.x));
            atomicMax((int*)&om[1], __float_as_int(lm.y));
            atomicMax((int*)&om[2], __float_as_int(lm.z));
            atomicMax((int*)&om[3], __float_as_int(lm.w));
            ls = make_float4(0.f, 0.f, 0.f, 0.f);
            lm = make_float4(0.f, 0.f, 0.f, 0.f);
            gcur = g;
        }
        float4 v = ldY4(h2, n, lane);
        float p = v.x * wp.x + v.y * wp.y + v.z * wp.z + v.w * wp.w;
        #pragma unroll
        for (int o = 16; o > 0; o >>= 1)
            p += __shfl_xor_sync(0xFFFFFFFFu, p, o);
        float w = 1.0f / (1.0f + expf(-(p + bpv)));
        ls.x += v.x * w; ls.y += v.y * w; ls.z += v.z * w; ls.w += v.w * w;
        lm.x = fmaxf(lm.x, v.x); lm.y = fmaxf(lm.y, v.y);
        lm.z = fmaxf(lm.z, v.z); lm.w = fmaxf(lm.w, v.w);
    }
    float* os = &out[gcur * 2 * HDIM + lane * 4];
    float* om = os + HDIM;
    atomicAdd(&os[0], ls.x); atomicAdd(&os[1], ls.y);
    atomicAdd(&os[2], ls.z); atomicAdd(&os[3], ls.w);
    atomicMax((int*)&om[0], __float_as_int(lm.x));
    atomicMax((int*)&om[1], __float_as_int(lm.y));
    atomicMax((int*)&om[2], __float_as_int(lm.z));
    atomicMax((int*)&om[3], __float_as_int(lm.w));
}

// ---------------- launch ----------------
extern "C" void kernel_launch(void* const* d_in, const int* in_sizes, int n_in,
                              void* d_out, int out_size) {
    const float* node_feats = (const float*)d_in[0];
    const int*   src        = (const int*)d_in[1];
    const int*   dst        = (const int*)d_in[2];
    const int*   gid        = (const int*)d_in[3];
    const float* W1 = (const float*)d_in[4];  const float* b1 = (const float*)d_in[5];
    const float* W2 = (const float*)d_in[6];  const float* b2 = (const float*)d_in[7];
    const float* W3 = (const float*)d_in[8];  const float* b3 = (const float*)d_in[9];
    const float* Wp = (const float*)d_in[10]; const float* bp = (const float*)d_in[11];
    float* out = (float*)d_out;

    const int N = in_sizes[0] / HDIM;
    const int E = in_sizes[1];

    float *pns, *pnd;
    __half *pY, *pu, *pW;
    int *pod, *pid_, *poff, *pcur, *pcsr, *pbs;
    cudaGetSymbolAddress((void**)&pY,  g_Y);
    cudaGetSymbolAddress((void**)&pu,  g_u);
    cudaGetSymbolAddress((void**)&pW,  g_W);
    cudaGetSymbolAddress((void**)&pns, g_ns);
    cudaGetSymbolAddress((void**)&pnd, g_nd);
    cudaGetSymbolAddress((void**)&pod, g_odeg);
    cudaGetSymbolAddress((void**)&pid_, g_ideg);
    cudaGetSymbolAddress((void**)&poff, g_off);
    cudaGetSymbolAddress((void**)&pcur, g_cursor);
    cudaGetSymbolAddress((void**)&pcsr, g_csr_src);
    cudaGetSymbolAddress((void**)&pbs, g_bsums);

    cudaFuncSetAttribute(mma_gemm_kernel,
                         cudaFuncAttributeMaxDynamicSharedMemorySize, SMEM_MMA);

    const int nblk_scan = (N + SCAN_BLK - 1) / SCAN_BLK;
    const int gemm_grid = (N + 127) / 128;
    const int gather_blocks = (int)(((long long)N * 32 + 255) / 256);

    // --- fork: CSR/norm build on side stream; conversions + GEMM1 on main ---
    cudaStream_t sB;
    cudaStreamCreateWithFlags(&sB, cudaStreamNonBlocking);
    cudaEvent_t evFork, evJoin;
    cudaEventCreateWithFlags(&evFork, cudaEventDisableTiming);
    cudaEventCreateWithFlags(&evJoin, cudaEventDisableTiming);

    cudaEventRecord(evFork, 0);
    cudaStreamWaitEvent(sB, evFork, 0);

    cudaMemsetAsync(pod, 0, (size_t)N * sizeof(int), sB);
    cudaMemsetAsync(pid_, 0, (size_t)N * sizeof(int), sB);
    count_deg_kernel<<<(E + 255) / 256, 256, 0, sB>>>(src, dst, pod, pid_, E);
    norms_kernel<<<(N + 255) / 256, 256, 0, sB>>>(pod, pid_, pns, pnd, N);
    blocksum_kernel<<<nblk_scan, SCAN_BLK, 0, sB>>>(pid_, pbs, N);
    scan_bsums_kernel<<<1, MAX_BLKS, 0, sB>>>(pbs, nblk_scan);
    write_offsets_kernel<<<nblk_scan, SCAN_BLK, 0, sB>>>(pid_, pbs, poff, pcur, N);
    fill_csr_kernel<<<(E + 255) / 256, 256, 0, sB>>>(src, dst, pcur, pcsr, E);
    zero_out_kernel<<<(out_size + 255) / 256, 256, 0, sB>>>(out, out_size);

    // main: W + X conversion, GEMM1 (independent of norms/CSR)
    convertW_kernel<<<(3 * HDIM * HDIM + 255) / 256, 256>>>(W1, W2, W3, pW);
    convertX_kernel<<<(N * 32 + 255) / 256, 256>>>(node_feats, pu, N * 32);
    mma_gemm_kernel<<<gemm_grid, 512, SMEM_MMA>>>(pu, pW, pY, N);

    cudaEventRecord(evJoin, sB);
    cudaStreamWaitEvent(0, evJoin, 0);

    // --- layer 1 gather (per-edge ns), then layers 2-3 (serial) ---
    gather_kernel<<<gather_blocks, 256>>>(pY, poff, pid_, pcsr, pns, pnd, b1,
                                          pu, 0, N);
    mma_gemm_kernel<<<gemm_grid, 512, SMEM_MMA>>>(pu, pW + HDIM * HDIM, pY, N);
    gather_kernel<<<gather_blocks, 256>>>(pY, poff, pid_, pcsr, pns, pnd, b2,
                                          pu, 1, N);
    mma_gemm_kernel<<<gemm_grid, 512, SMEM_MMA>>>(pu, pW + 2 * HDIM * HDIM, pY, N);
    gather_kernel<<<gather_blocks, 256>>>(pY, poff, pid_, pcsr, pns, pnd, b3,
                                          pu, 2, N);

    pool_kernel<<<POOL_BLOCKS, POOL_TPB>>>(pu, gid, Wp, bp, out, N);
    // single side stream + 2 events, not destroyed (round-6-proven pattern)
}